// round 12
// baseline (speedup 1.0000x reference)
#include <cuda_runtime.h>
#include <cuda_bf16.h>
#include <stdint.h>
#include <math.h>

// ---------------------------------------------------------------------------
// HierarchicalClassifier, warp-specialized bf16 HMMA on sm_103a.
//   bottom logits[16384,128] = A[16384,2048] @ Wb[2048,128] via 3-term bf16
//   hi/lo split MMA (Ah*Bh + Ah*Bl + Al*Bh).
//   top-gate logits[16384,8] computed in fp32 FFMA by producer warps (free pipe).
// R10: MMA N = 128 (top-gate offloaded to FMA), consumer shape Wm=2 x Wn=4
//      (tile 64x32) to halve B LDSM traffic. 8 consumers + 4 producers.
// ---------------------------------------------------------------------------

#define D_K   2048

__device__ __nv_bfloat16 g_Bh[128 * D_K];    // bottom W, [n][k] K-major, bf16 hi
__device__ __nv_bfloat16 g_Bl[128 * D_K];    // bf16 lo
__device__ float         g_topWt[D_K * 8];   // topW transposed [k][t]
__device__ float         g_bias[136];        // [0,128) bottom, [128,136) top

// ---------------------------------------------------------------------------
__global__ void pack_kernel(const float* __restrict__ topW,
                            const float* __restrict__ topb,
                            const float* __restrict__ botW,
                            const float* __restrict__ botb) {
    int idx = blockIdx.x * blockDim.x + threadIdx.x;
    if (idx < 128 * D_K) {
        int n = idx / D_K, k = idx - n * D_K;
        int t = n >> 4, c = n & 15;
        float v = botW[((size_t)t * D_K + k) * 16 + c];
        __nv_bfloat16 hi = __float2bfloat16(v);
        g_Bh[idx] = hi;
        g_Bl[idx] = __float2bfloat16(v - __bfloat162float(hi));
    }
    if (idx < D_K * 8) {
        int k = idx >> 3, t = idx & 7;
        g_topWt[idx] = topW[t * D_K + k];
    }
    if (idx < 136) {
        g_bias[idx] = (idx < 128) ? botb[idx] : topb[idx - 128];
    }
}

// ---------------------------------------------------------------------------
__device__ __forceinline__ uint32_t smem_u32(const void* p) {
    uint32_t a;
    asm("{ .reg .u64 t; cvta.to.shared.u64 t, %1; cvt.u32.u64 %0, t; }"
        : "=r"(a) : "l"(p));
    return a;
}

#define LDSM_X4(r0, r1, r2, r3, addr) \
    asm volatile("ldmatrix.sync.aligned.m8n8.x4.shared.b16 {%0,%1,%2,%3}, [%4];" \
        : "=r"(r0), "=r"(r1), "=r"(r2), "=r"(r3) : "r"(addr))

#define MMA_BF16(d, a, b0, b1) \
    asm volatile("mma.sync.aligned.m16n8k16.row.col.f32.bf16.bf16.f32 " \
        "{%0,%1,%2,%3}, {%4,%5,%6,%7}, {%8,%9}, {%0,%1,%2,%3};" \
        : "+f"((d)[0]), "+f"((d)[1]), "+f"((d)[2]), "+f"((d)[3]) \
        : "r"((a)[0]), "r"((a)[1]), "r"((a)[2]), "r"((a)[3]), \
          "r"(b0), "r"(b1))

#define CP16(dst, src) \
    asm volatile("cp.async.cg.shared.global [%0], [%1], 16;" \
        :: "r"(dst), "l"(src) : "memory")
#define CP_COMMIT() asm volatile("cp.async.commit_group;" ::: "memory")
#define CP_WAIT0()  asm volatile("cp.async.wait_group 0;" ::: "memory")

#define BAR_SYNC(id)   asm volatile("bar.sync %0, 384;"   :: "r"(id) : "memory")
#define BAR_ARRIVE(id) asm volatile("bar.arrive %0, 384;" :: "r"(id) : "memory")

__device__ __forceinline__ void split2(float v0, float v1, uint32_t& h, uint32_t& l) {
    uint32_t hp;
    asm("cvt.rn.bf16x2.f32 %0, %1, %2;" : "=r"(hp) : "f"(v1), "f"(v0));
    float h0 = __uint_as_float(hp << 16);
    float h1 = __uint_as_float(hp & 0xffff0000u);
    uint32_t lp;
    asm("cvt.rn.bf16x2.f32 %0, %1, %2;" : "=r"(lp) : "f"(v1 - h1), "f"(v0 - h0));
    h = hp; l = lp;
}

// ---------------------------------------------------------------------------
// Stage layout (pitch 144B = 128B data + 16B pad):
//   Ahi @0 (128*144=18432) | Alo @18432 | Bhi @36864 (128*144) | Blo @55296
// STAGE = 73728, double buffered. topL (128x8 f32) @ 2*STAGE.
// ---------------------------------------------------------------------------
constexpr int PITCH    = 144;
constexpr int AHI_OFF  = 0;
constexpr int ALO_OFF  = 18432;
constexpr int BHI_OFF  = 36864;
constexpr int BLO_OFF  = 55296;
constexpr int STAGE    = 73728;
constexpr int TOPL_OFF = 2 * STAGE;
constexpr int SMEM_DYN = 2 * STAGE + 128 * 8 * 4;   // 151552

constexpr int NTHR  = 384;     // 8 consumer warps + 4 producer warps
constexpr int NCONS = 8;
constexpr int LPITCH = 136;    // logits restage pitch (floats), bank-friendly

#define FULL_BAR(s) (1 + (s))
#define FREE_BAR(s) (3 + (s))

__global__ __launch_bounds__(NTHR, 1)
void hc_mma_kernel(const float* __restrict__ A, float* __restrict__ out) {
    extern __shared__ char sm[];
    const int tid  = threadIdx.x;
    const int wid  = tid >> 5, lane = tid & 31;
    const int row0 = blockIdx.x * 128;
    const uint32_t smu = smem_u32(sm);

    if (wid < NCONS) {
        // =============================== CONSUMER ===========================
        // 2 M-warps x 4 N-warps; warp computes 64 x 32
        const int m0 = (wid & 1) * 64;
        const int n0 = (wid >> 1) * 32;
        const int frow = lane & 15;
        const int fk   = (lane >> 4) * 8;

        float acc[4][4][4];   // [mt 16-row tiles][n8 within 32 cols][4]
        #pragma unroll
        for (int mt = 0; mt < 4; mt++)
            #pragma unroll
            for (int j = 0; j < 4; j++)
                #pragma unroll
                for (int e = 0; e < 4; e++) acc[mt][j][e] = 0.0f;

        for (int ck = 0; ck < 32; ck++) {
            const int s = ck & 1;
            BAR_SYNC(FULL_BAR(s));

            uint32_t stg  = smu + s * STAGE;
            uint32_t aHiB = stg + AHI_OFF, aLoB = stg + ALO_OFF;
            uint32_t bHiB = stg + BHI_OFF, bLoB = stg + BLO_OFF;

            #pragma unroll
            for (int ks = 0; ks < 4; ks++) {
                const int kk = ks * 16;
                uint32_t ah[4][4], al[4][4];
                #pragma unroll
                for (int mt = 0; mt < 4; mt++) {
                    uint32_t ra = (uint32_t)((m0 + mt * 16 + frow) * PITCH + (kk + fk) * 2);
                    LDSM_X4(ah[mt][0], ah[mt][1], ah[mt][2], ah[mt][3], aHiB + ra);
                    LDSM_X4(al[mt][0], al[mt][1], al[mt][2], al[mt][3], aLoB + ra);
                }
                uint32_t bh[2][4], bl[2][4];
                #pragma unroll
                for (int g = 0; g < 2; g++) {
                    uint32_t rb = (uint32_t)((n0 + g * 16 + frow) * PITCH + (kk + fk) * 2);
                    LDSM_X4(bh[g][0], bh[g][1], bh[g][2], bh[g][3], bHiB + rb);
                    LDSM_X4(bl[g][0], bl[g][1], bl[g][2], bl[g][3], bLoB + rb);
                }
                // 48 MMAs, term-major (8 independent acc chains per term)
                #pragma unroll
                for (int g = 0; g < 2; g++) {
                    #pragma unroll
                    for (int mt = 0; mt < 4; mt++) {
                        MMA_BF16(acc[mt][2*g],   ah[mt], bh[g][0], bh[g][2]);
                        MMA_BF16(acc[mt][2*g+1], ah[mt], bh[g][1], bh[g][3]);
                    }
                    #pragma unroll
                    for (int mt = 0; mt < 4; mt++) {
                        MMA_BF16(acc[mt][2*g],   ah[mt], bl[g][0], bl[g][2]);
                        MMA_BF16(acc[mt][2*g+1], ah[mt], bl[g][1], bl[g][3]);
                    }
                    #pragma unroll
                    for (int mt = 0; mt < 4; mt++) {
                        MMA_BF16(acc[mt][2*g],   al[mt], bh[g][0], bh[g][2]);
                        MMA_BF16(acc[mt][2*g+1], al[mt], bh[g][1], bh[g][3]);
                    }
                }
            }
            BAR_ARRIVE(FREE_BAR(s));
        }

        // restage bottom logits (+bias) into stage-0 area, [128][LPITCH] f32
        float* Ls = (float*)sm;
        const int rr = lane >> 2;
        const int cc = (lane & 3) * 2;
        #pragma unroll
        for (int mt = 0; mt < 4; mt++)
            #pragma unroll
            for (int j = 0; j < 4; j++) {
                int r = m0 + mt * 16 + rr;
                int c = n0 + j * 8 + cc;
                float b0 = g_bias[c], b1 = g_bias[c + 1];
                Ls[r * LPITCH + c]           = acc[mt][j][0] + b0;
                Ls[r * LPITCH + c + 1]       = acc[mt][j][1] + b1;
                Ls[(r + 8) * LPITCH + c]     = acc[mt][j][2] + b0;
                Ls[(r + 8) * LPITCH + c + 1] = acc[mt][j][3] + b1;
            }
    } else {
        // =============================== PRODUCER ===========================
        const int tp = tid - NCONS * 32;          // 0..127, one A row each
        const float* aRow = A + (size_t)(row0 + tp) * D_K;
        char* aDst = sm + tp * PITCH;

        float4 av[16];
        float gacc[8];
        #pragma unroll
        for (int t = 0; t < 8; t++) gacc[t] = 0.0f;

        auto ldgA = [&](int kt) {
            #pragma unroll
            for (int q = 0; q < 16; q++)
                av[q] = *(const float4*)(aRow + kt + q * 4);
        };
        auto cpB = [&](int kt, int s) {
            uint32_t bBase = smu + s * STAGE + BHI_OFF;
            #pragma unroll
            for (int p = 0; p < 16; p++) {
                int i = tp + p * 128;               // 0..2047 exactly
                int half = (i >= 1024) ? 1 : 0;
                int j = i - half * 1024;
                int n = j >> 3, seg = j & 7;
                const __nv_bfloat16* src =
                    (half ? g_Bl : g_Bh) + (size_t)n * D_K + kt + seg * 8;
                uint32_t dst = bBase + half * 18432 + n * PITCH + seg * 16;
                CP16(dst, src);
            }
        };
        auto stsA = [&](int s) {
            char* d = aDst + s * STAGE;
            #pragma unroll
            for (int q = 0; q < 4; q++) {
                uint32_t hi[8], lo[8];
                #pragma unroll
                for (int x = 0; x < 4; x++) {
                    split2(av[4*q+x].x, av[4*q+x].y, hi[2*x],   lo[2*x]);
                    split2(av[4*q+x].z, av[4*q+x].w, hi[2*x+1], lo[2*x+1]);
                }
                *(uint4*)(d + AHI_OFF + q * 32)      = make_uint4(hi[0], hi[1], hi[2], hi[3]);
                *(uint4*)(d + AHI_OFF + q * 32 + 16) = make_uint4(hi[4], hi[5], hi[6], hi[7]);
                *(uint4*)(d + ALO_OFF + q * 32)      = make_uint4(lo[0], lo[1], lo[2], lo[3]);
                *(uint4*)(d + ALO_OFF + q * 32 + 16) = make_uint4(lo[4], lo[5], lo[6], lo[7]);
            }
        };
        auto gateAcc = [&](int kt) {
            const float4* w4 = (const float4*)(g_topWt + (size_t)kt * 8);
            #pragma unroll
            for (int q = 0; q < 16; q++) {
                #pragma unroll
                for (int x = 0; x < 4; x++) {
                    float a = (x == 0) ? av[q].x : (x == 1) ? av[q].y
                            : (x == 2) ? av[q].z : av[q].w;
                    float4 w0 = __ldg(&w4[(q * 4 + x) * 2]);
                    float4 w1 = __ldg(&w4[(q * 4 + x) * 2 + 1]);
                    gacc[0] = fmaf(a, w0.x, gacc[0]);
                    gacc[1] = fmaf(a, w0.y, gacc[1]);
                    gacc[2] = fmaf(a, w0.z, gacc[2]);
                    gacc[3] = fmaf(a, w0.w, gacc[3]);
                    gacc[4] = fmaf(a, w1.x, gacc[4]);
                    gacc[5] = fmaf(a, w1.y, gacc[5]);
                    gacc[6] = fmaf(a, w1.z, gacc[6]);
                    gacc[7] = fmaf(a, w1.w, gacc[7]);
                }
            }
        };

        // prologue: fill both buffers
        ldgA(0);   cpB(0, 0);  stsA(0);  gateAcc(0);
        CP_COMMIT(); CP_WAIT0(); BAR_ARRIVE(FULL_BAR(0));
        ldgA(64);  cpB(64, 1); stsA(1);  gateAcc(64);
        CP_COMMIT(); CP_WAIT0(); BAR_ARRIVE(FULL_BAR(1));

        for (int ck = 2; ck < 32; ck++) {
            const int s = ck & 1;
            ldgA(ck * 64);                 // LDG in flight across the FREE wait
            BAR_SYNC(FREE_BAR(s));
            cpB(ck * 64, s);
            stsA(s);
            gateAcc(ck * 64);
            CP_COMMIT();
            CP_WAIT0();
            BAR_ARRIVE(FULL_BAR(s));
        }

        // write top-gate logits
        float* topL = (float*)(sm + TOPL_OFF);
        #pragma unroll
        for (int t = 0; t < 8; t++) topL[tp * 8 + t] = gacc[t];
    }

    __syncthreads();

    // ---- epilogue: 128 rows x 8 top-labels = 1024 tasks ----
    const float* Ls   = (const float*)sm;
    const float* topL = (const float*)(sm + TOPL_OFF);
    #pragma unroll
    for (int p = 0; p < 3; p++) {
        int task = tid + p * NTHR;
        if (task < 1024) {
            int r = task >> 3, t = task & 7;
            const float* Lr = Ls + r * LPITCH;

            float gate = 1.0f / (1.0f + __expf(-(topL[r * 8 + t] + g_bias[128 + t])));

            float l[16], mx = -1e30f;
            #pragma unroll
            for (int c = 0; c < 16; c++) {
                l[c] = Lr[t * 16 + c];
                mx = fmaxf(mx, l[c]);
            }
            float ssum = 0.0f;
            #pragma unroll
            for (int c = 0; c < 16; c++) { l[c] = __expf(l[c] - mx); ssum += l[c]; }
            float sc = gate / ssum;

            float* op = out + (size_t)(row0 + r) * 128 + t * 16;
            #pragma unroll
            for (int q = 0; q < 4; q++) {
                float4 v;
                v.x = l[q * 4 + 0] * sc;
                v.y = l[q * 4 + 1] * sc;
                v.z = l[q * 4 + 2] * sc;
                v.w = l[q * 4 + 3] * sc;
                ((float4*)op)[q] = v;
            }
        }
    }
}

// ---------------------------------------------------------------------------
extern "C" void kernel_launch(void* const* d_in, const int* in_sizes, int n_in,
                              void* d_out, int out_size) {
    const float* features = (const float*)d_in[0];
    const float* topW     = (const float*)d_in[1];
    const float* topb     = (const float*)d_in[2];
    const float* botW     = (const float*)d_in[3];
    const float* botb     = (const float*)d_in[4];
    float* out = (float*)d_out;

    cudaFuncSetAttribute(hc_mma_kernel,
                         cudaFuncAttributeMaxDynamicSharedMemorySize, SMEM_DYN);

    pack_kernel<<<(128 * D_K + 255) / 256, 256>>>(topW, topb, botW, botb);
    hc_mma_kernel<<<16384 / 128, NTHR, SMEM_DYN>>>(features, out);
}

// round 14
// speedup vs baseline: 1.5922x; 1.5922x over previous
#include <cuda_runtime.h>
#include <cuda_bf16.h>
#include <stdint.h>
#include <math.h>

// ---------------------------------------------------------------------------
// HierarchicalClassifier, warp-specialized bf16 HMMA on sm_103a.
//   logits[16384,160pad] = A[16384,2048] @ Wpacked[2048,160] via 3-term bf16
//   hi/lo split (Ah*Bh + Ah*Bl + Al*Bh). Cols: [0,128) bottom, [128,136) gate,
//   [136,160) zero pad.
// R13: R12 with stsA fill bug fixed (8x16B units per A row, was 4 -> NaN).
//      16 consumer warps (4Mx4N, tile 32x40, 4/SMSP) + 4 producers (1/SMSP),
//      3-stage XOR-swizzled SMEM pipeline (pitch 128, no pad), 640 threads.
// ---------------------------------------------------------------------------

#define D_K   2048
#define N_PAD 160

__device__ __nv_bfloat16 g_Bh[N_PAD * D_K];   // [n][k] K-major, bf16 hi
__device__ __nv_bfloat16 g_Bl[N_PAD * D_K];   // bf16 lo
__device__ float         g_bias[144];         // [0,128) bottom, [128,136) top, pad 0

// ---------------------------------------------------------------------------
__global__ void pack_kernel(const float* __restrict__ topW,
                            const float* __restrict__ topb,
                            const float* __restrict__ botW,
                            const float* __restrict__ botb) {
    int idx = blockIdx.x * blockDim.x + threadIdx.x;
    if (idx < N_PAD * D_K) {
        int n = idx / D_K, k = idx - n * D_K;
        float v = 0.0f;
        if (n < 128) {
            int t = n >> 4, c = n & 15;
            v = botW[((size_t)t * D_K + k) * 16 + c];
        } else if (n < 136) {
            v = topW[(n - 128) * D_K + k];
        }
        __nv_bfloat16 hi = __float2bfloat16(v);
        g_Bh[idx] = hi;
        g_Bl[idx] = __float2bfloat16(v - __bfloat162float(hi));
    }
    if (idx < 144) {
        float b = 0.0f;
        if (idx < 128)      b = botb[idx];
        else if (idx < 136) b = topb[idx - 128];
        g_bias[idx] = b;
    }
}

// ---------------------------------------------------------------------------
__device__ __forceinline__ uint32_t smem_u32(const void* p) {
    uint32_t a;
    asm("{ .reg .u64 t; cvta.to.shared.u64 t, %1; cvt.u32.u64 %0, t; }"
        : "=r"(a) : "l"(p));
    return a;
}

#define LDSM_X4(r0, r1, r2, r3, addr) \
    asm volatile("ldmatrix.sync.aligned.m8n8.x4.shared.b16 {%0,%1,%2,%3}, [%4];" \
        : "=r"(r0), "=r"(r1), "=r"(r2), "=r"(r3) : "r"(addr))

#define LDSM_X2(r0, r1, addr) \
    asm volatile("ldmatrix.sync.aligned.m8n8.x2.shared.b16 {%0,%1}, [%2];" \
        : "=r"(r0), "=r"(r1) : "r"(addr))

#define MMA_BF16(d, a, b0, b1) \
    asm volatile("mma.sync.aligned.m16n8k16.row.col.f32.bf16.bf16.f32 " \
        "{%0,%1,%2,%3}, {%4,%5,%6,%7}, {%8,%9}, {%0,%1,%2,%3};" \
        : "+f"((d)[0]), "+f"((d)[1]), "+f"((d)[2]), "+f"((d)[3]) \
        : "r"((a)[0]), "r"((a)[1]), "r"((a)[2]), "r"((a)[3]), \
          "r"(b0), "r"(b1))

#define CP16(dst, src) \
    asm volatile("cp.async.cg.shared.global [%0], [%1], 16;" \
        :: "r"(dst), "l"(src) : "memory")
#define CP_COMMIT() asm volatile("cp.async.commit_group;" ::: "memory")
#define CP_WAIT0()  asm volatile("cp.async.wait_group 0;" ::: "memory")

#define BAR_SYNC(id)   asm volatile("bar.sync %0, 640;"   :: "r"(id) : "memory")
#define BAR_ARRIVE(id) asm volatile("bar.arrive %0, 640;" :: "r"(id) : "memory")

__device__ __forceinline__ void split2(float v0, float v1, uint32_t& h, uint32_t& l) {
    uint32_t hp;
    asm("cvt.rn.bf16x2.f32 %0, %1, %2;" : "=r"(hp) : "f"(v1), "f"(v0));
    float h0 = __uint_as_float(hp << 16);
    float h1 = __uint_as_float(hp & 0xffff0000u);
    uint32_t lp;
    asm("cvt.rn.bf16x2.f32 %0, %1, %2;" : "=r"(lp) : "f"(v1 - h1), "f"(v0 - h0));
    h = hp; l = lp;
}

// XOR swizzle: 16B unit u of row -> u ^ (row & 7). Pitch 128B, no pad.
#define SWZ16(row, u) ((uint32_t)(((u) ^ ((row) & 7)) << 4))

// ---------------------------------------------------------------------------
// Stage (pitch 128B): Ahi @0 (16384) | Alo @16384 | Bhi @32768 (20480) | Blo @53248
// STAGE = 73728, 3 stages = 221184.
// ---------------------------------------------------------------------------
constexpr int AHI_OFF  = 0;
constexpr int ALO_OFF  = 16384;
constexpr int BHI_OFF  = 32768;
constexpr int BLO_OFF  = 53248;
constexpr int STAGE    = 73728;
constexpr int NSTAGE   = 3;
constexpr int SMEM_DYN = NSTAGE * STAGE;   // 221184

constexpr int NTHR  = 640;     // 16 consumer warps + 4 producer warps
constexpr int NCONS = 16;
constexpr int LPITCH = 144;    // logits restage pitch (floats); fits in stage0

#define FULL_BAR(s) (1 + (s))
#define FREE_BAR(s) (4 + (s))

__global__ __launch_bounds__(NTHR, 1)
void hc_mma_kernel(const float* __restrict__ A, float* __restrict__ out) {
    extern __shared__ char sm[];
    const int tid  = threadIdx.x;
    const int wid  = tid >> 5, lane = tid & 31;
    const int row0 = blockIdx.x * 128;
    const uint32_t smu = smem_u32(sm);

    if (wid < NCONS) {
        // =============================== CONSUMER ===========================
        // 4 M-warps x 4 N-warps; warp tile 32 x 40 (2x16-col groups + 8-col tail)
        const int m0 = (wid & 3) * 32;
        const int n0 = (wid >> 2) * 40;
        const int frow = lane & 15;
        const int u16  = lane >> 4;            // x4: +0/+1 16B unit
        const int xrow = lane & 7;             // x2 lane mapping
        const int xu   = (lane >> 3) & 1;

        float acc[2][5][4];   // [mt][n8: 0..3 groups, 4 tail][4]
        #pragma unroll
        for (int mt = 0; mt < 2; mt++)
            #pragma unroll
            for (int j = 0; j < 5; j++)
                #pragma unroll
                for (int e = 0; e < 4; e++) acc[mt][j][e] = 0.0f;

        int s = 0;
        for (int ck = 0; ck < 32; ck++) {
            BAR_SYNC(FULL_BAR(s));
            uint32_t stg  = smu + s * STAGE;
            uint32_t aHiB = stg + AHI_OFF;
            uint32_t bHiB = stg + BHI_OFF;

            #pragma unroll
            for (int ks = 0; ks < 4; ks++) {
                const int u0 = ks * 2 + u16;
                uint32_t ah[2][4], al[2][4];
                #pragma unroll
                for (int mt = 0; mt < 2; mt++) {
                    int row = m0 + mt * 16 + frow;
                    uint32_t ad = aHiB + row * 128 + SWZ16(row, u0);
                    LDSM_X4(ah[mt][0], ah[mt][1], ah[mt][2], ah[mt][3], ad);
                    LDSM_X4(al[mt][0], al[mt][1], al[mt][2], al[mt][3],
                            ad + (ALO_OFF - AHI_OFF));
                }
                #pragma unroll
                for (int g = 0; g < 2; g++) {
                    int row = n0 + g * 16 + frow;
                    uint32_t bd = bHiB + row * 128 + SWZ16(row, u0);
                    uint32_t h0, h1, h2, h3, l0, l1, l2, l3;
                    LDSM_X4(h0, h1, h2, h3, bd);
                    LDSM_X4(l0, l1, l2, l3, bd + (BLO_OFF - BHI_OFF));
                    #pragma unroll
                    for (int mt = 0; mt < 2; mt++) {
                        MMA_BF16(acc[mt][2*g],   ah[mt], h0, h2);
                        MMA_BF16(acc[mt][2*g+1], ah[mt], h1, h3);
                    }
                    #pragma unroll
                    for (int mt = 0; mt < 2; mt++) {
                        MMA_BF16(acc[mt][2*g],   ah[mt], l0, l2);
                        MMA_BF16(acc[mt][2*g+1], ah[mt], l1, l3);
                    }
                    #pragma unroll
                    for (int mt = 0; mt < 2; mt++) {
                        MMA_BF16(acc[mt][2*g],   al[mt], h0, h2);
                        MMA_BF16(acc[mt][2*g+1], al[mt], h1, h3);
                    }
                }
                {   // 8-col tail: rows n0+32..n0+40
                    int row = n0 + 32 + xrow;
                    int u = ks * 2 + xu;
                    uint32_t bd = bHiB + row * 128 + SWZ16(row, u);
                    uint32_t xh0, xh1, xl0, xl1;
                    LDSM_X2(xh0, xh1, bd);
                    LDSM_X2(xl0, xl1, bd + (BLO_OFF - BHI_OFF));
                    #pragma unroll
                    for (int mt = 0; mt < 2; mt++) MMA_BF16(acc[mt][4], ah[mt], xh0, xh1);
                    #pragma unroll
                    for (int mt = 0; mt < 2; mt++) MMA_BF16(acc[mt][4], ah[mt], xl0, xl1);
                    #pragma unroll
                    for (int mt = 0; mt < 2; mt++) MMA_BF16(acc[mt][4], al[mt], xh0, xh1);
                }
            }
            BAR_ARRIVE(FREE_BAR(s));
            if (++s == NSTAGE) s = 0;
        }

        // restage logits (+bias) into [128][LPITCH] f32 in stage0 (all consumers
        // have passed ck=30's stage0 read before any restage can begin)
        float* Ls = (float*)sm;
        const int rr = lane >> 2;
        const int cc = (lane & 3) * 2;
        #pragma unroll
        for (int mt = 0; mt < 2; mt++)
            #pragma unroll
            for (int j = 0; j < 5; j++) {
                int r = m0 + mt * 16 + rr;
                int c = n0 + j * 8 + cc;
                if (c < 144) {
                    float b0 = g_bias[c], b1 = g_bias[c + 1];
                    Ls[r * LPITCH + c]           = acc[mt][j][0] + b0;
                    Ls[r * LPITCH + c + 1]       = acc[mt][j][1] + b1;
                    Ls[(r + 8) * LPITCH + c]     = acc[mt][j][2] + b0;
                    Ls[(r + 8) * LPITCH + c + 1] = acc[mt][j][3] + b1;
                }
            }
    } else {
        // =============================== PRODUCER ===========================
        const int tp = tid - NCONS * 32;          // 0..127, one A row each
        const float* aRow = A + (size_t)(row0 + tp) * D_K;

        float4 av[16];
        auto ldgA = [&](int kt) {
            #pragma unroll
            for (int q = 0; q < 16; q++)
                av[q] = *(const float4*)(aRow + kt + q * 4);
        };
        auto cpB = [&](int kt, int s) {
            uint32_t bBase = smu + s * STAGE + BHI_OFF;
            #pragma unroll
            for (int p = 0; p < 20; p++) {
                int i = tp + p * 128;               // 0..2559 exactly
                int half = (i >= 1280) ? 1 : 0;
                int j = i - half * 1280;
                int n = j >> 3, seg = j & 7;
                const __nv_bfloat16* src =
                    (half ? g_Bl : g_Bh) + (size_t)n * D_K + kt + seg * 8;
                uint32_t dst = bBase + half * (BLO_OFF - BHI_OFF)
                             + n * 128 + SWZ16(n, seg);
                CP16(dst, src);
            }
        };
        auto stsA = [&](int s) {
            char* d = sm + s * STAGE + tp * 128;
            #pragma unroll
            for (int q = 0; q < 8; q++) {           // FIX: all 8 16B units per row
                uint32_t hi[4], lo[4];
                split2(av[2*q].x,   av[2*q].y,   hi[0], lo[0]);
                split2(av[2*q].z,   av[2*q].w,   hi[1], lo[1]);
                split2(av[2*q+1].x, av[2*q+1].y, hi[2], lo[2]);
                split2(av[2*q+1].z, av[2*q+1].w, hi[3], lo[3]);
                uint32_t sw = SWZ16(tp, q);
                *(uint4*)(d + AHI_OFF + sw) = make_uint4(hi[0], hi[1], hi[2], hi[3]);
                *(uint4*)(d + ALO_OFF + sw) = make_uint4(lo[0], lo[1], lo[2], lo[3]);
            }
        };

        // prologue: fill all 3 stages
        #pragma unroll
        for (int ck = 0; ck < 3; ck++) {
            ldgA(ck * 64);
            cpB(ck * 64, ck);
            stsA(ck);
            CP_COMMIT(); CP_WAIT0();
            BAR_ARRIVE(FULL_BAR(ck));
        }

        int s = 0;
        for (int ck = 3; ck < 32; ck++) {
            ldgA(ck * 64);                 // LDG in flight across the FREE wait
            BAR_SYNC(FREE_BAR(s));
            cpB(ck * 64, s);
            stsA(s);
            CP_COMMIT(); CP_WAIT0();
            BAR_ARRIVE(FULL_BAR(s));
            if (++s == NSTAGE) s = 0;
        }
    }

    __syncthreads();

    // ---- epilogue: 128 rows x 8 top-labels = 1024 tasks ----
    const float* Ls = (const float*)sm;
    #pragma unroll
    for (int p = 0; p < 2; p++) {
        int task = tid + p * NTHR;
        if (task < 1024) {
            int r = task >> 3, t = task & 7;
            const float* Lr = Ls + r * LPITCH;

            float gate = 1.0f / (1.0f + __expf(-Lr[128 + t]));

            float l[16], mx = -1e30f;
            #pragma unroll
            for (int c = 0; c < 16; c++) {
                l[c] = Lr[t * 16 + c];
                mx = fmaxf(mx, l[c]);
            }
            float ssum = 0.0f;
            #pragma unroll
            for (int c = 0; c < 16; c++) { l[c] = __expf(l[c] - mx); ssum += l[c]; }
            float sc = gate / ssum;

            float* op = out + (size_t)(row0 + r) * 128 + t * 16;
            #pragma unroll
            for (int q = 0; q < 4; q++) {
                float4 v;
                v.x = l[q * 4 + 0] * sc;
                v.y = l[q * 4 + 1] * sc;
                v.z = l[q * 4 + 2] * sc;
                v.w = l[q * 4 + 3] * sc;
                ((float4*)op)[q] = v;
            }
        }
    }
}

// ---------------------------------------------------------------------------
extern "C" void kernel_launch(void* const* d_in, const int* in_sizes, int n_in,
                              void* d_out, int out_size) {
    const float* features = (const float*)d_in[0];
    const float* topW     = (const float*)d_in[1];
    const float* topb     = (const float*)d_in[2];
    const float* botW     = (const float*)d_in[3];
    const float* botb     = (const float*)d_in[4];
    float* out = (float*)d_out;

    cudaFuncSetAttribute(hc_mma_kernel,
                         cudaFuncAttributeMaxDynamicSharedMemorySize, SMEM_DYN);

    pack_kernel<<<(N_PAD * D_K + 255) / 256, 256>>>(topW, topb, botW, botb);
    hc_mma_kernel<<<16384 / 128, NTHR, SMEM_DYN>>>(features, out);
}